// round 13
// baseline (speedup 1.0000x reference)
#include <cuda_runtime.h>

namespace {
constexpr int P    = 32;
constexpr int Cin  = 9;
constexpr int H    = 64;
constexpr int OUTC = 128;
constexpr int FS   = 36;   // fT row stride (floats); 16B-aligned rows
constexpr float EPS = 1e-5f;
}

// Main-loop weights live in the constant bank (separate cache port; frees
// l1tex wavefronts). 2304 + 32768 + 16384 = 51456 B < 64 KB.
__constant__ float cw_pre[Cin * H];
__constant__ float cw_m1[2 * H * H];   // full [128,64]: rows 0..63 main, 64..127 pctr
__constant__ float cw_m2[H * H];

using ull = unsigned long long;

struct SB {
  float  fT[2][H][FS];     // activations [q][channel][point]; pre-layer overlays ptsT here
  float  mk[2][P];
  float2 pooled2[H];       // {q0,q1} interleaved
  ull    part[2][H];       // split-k partials (pctr / o1)
  float2 pctr2[H];
  float2 feat2[H];
  float2 hid2[H];
  int    s_mode;
  int    s_valid[2];
};

__device__ __forceinline__ ull fma2(ull a, ull b, ull c) {
  ull d;
  asm("fma.rn.f32x2 %0, %1, %2, %3;" : "=l"(d) : "l"(a), "l"(b), "l"(c));
  return d;
}
__device__ __forceinline__ ull dup2(float x) {
  ull d; unsigned u = __float_as_uint(x);
  asm("mov.b64 %0, {%1, %1};" : "=l"(d) : "r"(u));
  return d;
}
__device__ __forceinline__ float2 unpk(ull v) {
  unsigned a, b;
  asm("mov.b64 {%0, %1}, %2;" : "=r"(a), "=r"(b) : "l"(v));
  return make_float2(__uint_as_float(a), __uint_as_float(b));
}
// BN fold, single channel, duplicated into both f32x2 lanes
__device__ __forceinline__ void bn1(const float* g, const float* be,
                                    const float* rm, const float* rv,
                                    const float* b, int h, ull& Ad, ull& Bd) {
  float s = __ldg(&g[h]) * rsqrtf(__ldg(&rv[h]) + EPS);
  float c = (__ldg(&b[h]) - __ldg(&rm[h])) * s + __ldg(&be[h]);
  Ad = dup2(s);
  Bd = dup2(c);
}

// 16 fma2: weights dup'd per channel, x arrives as packed point pairs
#define MMA_K(WV)                                                            \
  {                                                                          \
    ull wd0 = dup2((WV).x), wd1 = dup2((WV).y);                              \
    ull wd2 = dup2((WV).z), wd3 = dup2((WV).w);                              \
    ulonglong2 xa = *(const ulonglong2*)&sb->fT[0][k][p0];                   \
    ulonglong2 xb = *(const ulonglong2*)&sb->fT[1][k][p0];                   \
    acc[0][0][0]=fma2(xa.x,wd0,acc[0][0][0]); acc[0][0][1]=fma2(xa.y,wd0,acc[0][0][1]); \
    acc[0][1][0]=fma2(xa.x,wd1,acc[0][1][0]); acc[0][1][1]=fma2(xa.y,wd1,acc[0][1][1]); \
    acc[0][2][0]=fma2(xa.x,wd2,acc[0][2][0]); acc[0][2][1]=fma2(xa.y,wd2,acc[0][2][1]); \
    acc[0][3][0]=fma2(xa.x,wd3,acc[0][3][0]); acc[0][3][1]=fma2(xa.y,wd3,acc[0][3][1]); \
    acc[1][0][0]=fma2(xb.x,wd0,acc[1][0][0]); acc[1][0][1]=fma2(xb.y,wd0,acc[1][0][1]); \
    acc[1][1][0]=fma2(xb.x,wd1,acc[1][1][0]); acc[1][1][1]=fma2(xb.y,wd1,acc[1][1][1]); \
    acc[1][2][0]=fma2(xb.x,wd2,acc[1][2][0]); acc[1][2][1]=fma2(xb.y,wd2,acc[1][2][1]); \
    acc[1][3][0]=fma2(xb.x,wd3,acc[1][3][0]); acc[1][3][1]=fma2(xb.y,wd3,acc[1][3][1]); \
  }

__global__ void __launch_bounds__(128)
pnet_kernel(const float* __restrict__ poly,
            const void*  __restrict__ mask,
            const float* __restrict__ pre_b,
            const float* __restrict__ pre_g, const float* __restrict__ pre_be,
            const float* __restrict__ pre_rm, const float* __restrict__ pre_rv,
            const float* __restrict__ m1_b,
            const float* __restrict__ m1_g,  const float* __restrict__ m1_be,
            const float* __restrict__ m1_rm, const float* __restrict__ m1_rv,
            const float* __restrict__ m2_b,
            const float* __restrict__ m2_g,  const float* __restrict__ m2_be,
            const float* __restrict__ m2_rm, const float* __restrict__ m2_rv,
            const float* __restrict__ o1_w,  const float* __restrict__ o1_b,
            const float* __restrict__ o2_w,  const float* __restrict__ o2_b,
            float* __restrict__ out)
{
  __shared__ __align__(16) SB sbs;
  SB* sb = &sbs;

  const int blk = blockIdx.x;          // polylines 2*blk, 2*blk+1
  const int tid = threadIdx.x;         // 0..127
  const int cg  = tid >> 3;            // 0..15  -> 4 channels each
  const int pg  = tid & 7;             // 0..7   -> 4 points each
  const int h0  = cg * 4;
  const int p0  = pg * 4;

  // ---- mask dtype detection (int32 vs float32 vs byte) ----
  if (tid == 0) {
    const unsigned* w32 = (const unsigned*)mask;
    bool big = false, allf = true;
    #pragma unroll
    for (int i = 0; i < 32; i++) {
      unsigned v = w32[i];
      big  |= (v > 1u);
      allf &= (v == 0u || v == 0x3f800000u);
    }
    sb->s_mode = big ? (allf ? 1 : 2) : 0;
  }
  __syncthreads();
  const int mode = sb->s_mode;

  // ---- load points TRANSPOSED into fT overlay: ptsT[q][c][p] ----
  float* ptsT = (float*)sb->fT;        // 576 floats << fT region
  {
    const float* pp = poly + (long long)(2 * blk) * (P * Cin);
    for (int i = tid; i < 2 * P * Cin; i += 128) {
      int q = i / (P * Cin), r = i % (P * Cin);
      int p = r / Cin, c = r % Cin;
      ptsT[q * 288 + c * 32 + p] = pp[i];
    }
  }
  if (tid < 64) {
    int q = tid >> 5, t = tid & 31;
    int gi = (2 * blk + q) * P + t;
    float mv;
    if (mode == 2)      mv = ((const unsigned char*)mask)[gi] ? 1.f : 0.f;
    else if (mode == 1) mv = (((const float*)mask)[gi] != 0.f) ? 1.f : 0.f;
    else                mv = ((const int*)mask)[gi] ? 1.f : 0.f;
    sb->mk[q][t] = mv;
    unsigned bal = __ballot_sync(0xffffffffu, mv != 0.f);
    if (t == 0) sb->s_valid[q] = (bal != 0u) ? 1 : 0;
  }
  __syncthreads();

  ull acc[2][4][2];    // [q][channel][point-pair]
  ull Ad[4], Bd[4];

  // ================= pre layer: [P,9] @ [9,64] =============================
  #pragma unroll
  for (int q = 0; q < 2; q++)
    #pragma unroll
    for (int c = 0; c < 4; c++) { acc[q][c][0] = 0ull; acc[q][c][1] = 0ull; }

  #pragma unroll 3
  for (int k = 0; k < Cin; k++) {
    float4 wv = *(const float4*)&cw_pre[k * H + h0];
    ull wd0 = dup2(wv.x), wd1 = dup2(wv.y), wd2 = dup2(wv.z), wd3 = dup2(wv.w);
    ulonglong2 xa = *(const ulonglong2*)&ptsT[k * 32 + p0];
    ulonglong2 xb = *(const ulonglong2*)&ptsT[288 + k * 32 + p0];
    acc[0][0][0]=fma2(xa.x,wd0,acc[0][0][0]); acc[0][0][1]=fma2(xa.y,wd0,acc[0][0][1]);
    acc[0][1][0]=fma2(xa.x,wd1,acc[0][1][0]); acc[0][1][1]=fma2(xa.y,wd1,acc[0][1][1]);
    acc[0][2][0]=fma2(xa.x,wd2,acc[0][2][0]); acc[0][2][1]=fma2(xa.y,wd2,acc[0][2][1]);
    acc[0][3][0]=fma2(xa.x,wd3,acc[0][3][0]); acc[0][3][1]=fma2(xa.y,wd3,acc[0][3][1]);
    acc[1][0][0]=fma2(xb.x,wd0,acc[1][0][0]); acc[1][0][1]=fma2(xb.y,wd0,acc[1][0][1]);
    acc[1][1][0]=fma2(xb.x,wd1,acc[1][1][0]); acc[1][1][1]=fma2(xb.y,wd1,acc[1][1][1]);
    acc[1][2][0]=fma2(xb.x,wd2,acc[1][2][0]); acc[1][2][1]=fma2(xb.y,wd2,acc[1][2][1]);
    acc[1][3][0]=fma2(xb.x,wd3,acc[1][3][0]); acc[1][3][1]=fma2(xb.y,wd3,acc[1][3][1]);
  }
  #pragma unroll
  for (int c = 0; c < 4; c++) bn1(pre_g, pre_be, pre_rm, pre_rv, pre_b, h0 + c, Ad[c], Bd[c]);
  {
    float4 sv[2][4];
    #pragma unroll
    for (int q = 0; q < 2; q++) {
      float mv0 = sb->mk[q][p0],     mv1 = sb->mk[q][p0 + 1];
      float mv2 = sb->mk[q][p0 + 2], mv3 = sb->mk[q][p0 + 3];
      #pragma unroll
      for (int c = 0; c < 4; c++) {
        float2 rA = unpk(fma2(acc[q][c][0], Ad[c], Bd[c]));
        float2 rB = unpk(fma2(acc[q][c][1], Ad[c], Bd[c]));
        sv[q][c] = make_float4(fmaxf(rA.x, 0.f) * mv0, fmaxf(rA.y, 0.f) * mv1,
                               fmaxf(rB.x, 0.f) * mv2, fmaxf(rB.y, 0.f) * mv3);
      }
    }
    __syncthreads();   // all ptsT reads done before fT overwrite
    #pragma unroll
    for (int q = 0; q < 2; q++)
      #pragma unroll
      for (int c = 0; c < 4; c++)
        *(float4*)&sb->fT[q][h0 + c][p0] = sv[q][c];
  }
  __syncthreads();

  // ===== max-pool over points: thread = (q, channel) =======================
  {
    int q = tid >> 6, ch = tid & 63;
    const float4* row = (const float4*)&sb->fT[q][ch][0];
    float m = 0.f;
    #pragma unroll
    for (int g = 0; g < 8; g++) {
      float4 v = row[g];
      m = fmaxf(m, fmaxf(fmaxf(v.x, v.y), fmaxf(v.z, v.w)));
    }
    (&sb->pooled2[ch].x)[q] = m;
  }
  __syncthreads();

  const ull ONE = dup2(1.f);

  // pctr = pooled @ m1_w[64:128,:], split-k over 2 halves (constant weights)
  {
    int half = tid >> 6, ch = tid & 63;
    int kb = half * 32;
    ull a = 0ull;
    #pragma unroll 8
    for (int k = 0; k < 32; k++) {
      float wv = cw_m1[(H + kb + k) * H + ch];
      a = fma2(*(const ull*)&sb->pooled2[kb + k], dup2(wv), a);
    }
    sb->part[half][ch] = a;
  }
  __syncthreads();
  if (tid < 64) {
    ull s = fma2(sb->part[0][tid], ONE, sb->part[1][tid]);
    float2 r = unpk(s);
    sb->pctr2[tid] = r;
  }
  __syncthreads();

  // ================= m1: [P,64] @ m1_w[0:64,:] + pctr ======================
  #pragma unroll
  for (int c = 0; c < 4; c++) {
    float2 pc = sb->pctr2[h0 + c];
    acc[0][c][0] = acc[0][c][1] = dup2(pc.x);
    acc[1][c][0] = acc[1][c][1] = dup2(pc.y);
  }
  #pragma unroll 4
  for (int k = 0; k < H; k++) {
    float4 wv = *(const float4*)&cw_m1[k * H + h0];
    MMA_K(wv)
  }
  #pragma unroll
  for (int c = 0; c < 4; c++) bn1(m1_g, m1_be, m1_rm, m1_rv, m1_b, h0 + c, Ad[c], Bd[c]);
  {
    float4 sv[2][4];
    #pragma unroll
    for (int q = 0; q < 2; q++)
      #pragma unroll
      for (int c = 0; c < 4; c++) {
        float2 rA = unpk(fma2(acc[q][c][0], Ad[c], Bd[c]));
        float2 rB = unpk(fma2(acc[q][c][1], Ad[c], Bd[c]));
        sv[q][c] = make_float4(fmaxf(rA.x, 0.f), fmaxf(rA.y, 0.f),
                               fmaxf(rB.x, 0.f), fmaxf(rB.y, 0.f));
      }
    __syncthreads();   // all fT reads done
    #pragma unroll
    for (int q = 0; q < 2; q++)
      #pragma unroll
      for (int c = 0; c < 4; c++)
        *(float4*)&sb->fT[q][h0 + c][p0] = sv[q][c];
  }
  __syncthreads();

  // ================= m2: [P,64] @ [64,64], masked ==========================
  #pragma unroll
  for (int q = 0; q < 2; q++)
    #pragma unroll
    for (int c = 0; c < 4; c++) { acc[q][c][0] = 0ull; acc[q][c][1] = 0ull; }

  #pragma unroll 4
  for (int k = 0; k < H; k++) {
    float4 wv = *(const float4*)&cw_m2[k * H + h0];
    MMA_K(wv)
  }
  #pragma unroll
  for (int c = 0; c < 4; c++) bn1(m2_g, m2_be, m2_rm, m2_rv, m2_b, h0 + c, Ad[c], Bd[c]);
  {
    float4 sv[2][4];
    #pragma unroll
    for (int q = 0; q < 2; q++) {
      float mv0 = sb->mk[q][p0],     mv1 = sb->mk[q][p0 + 1];
      float mv2 = sb->mk[q][p0 + 2], mv3 = sb->mk[q][p0 + 3];
      #pragma unroll
      for (int c = 0; c < 4; c++) {
        float2 rA = unpk(fma2(acc[q][c][0], Ad[c], Bd[c]));
        float2 rB = unpk(fma2(acc[q][c][1], Ad[c], Bd[c]));
        sv[q][c] = make_float4(fmaxf(rA.x, 0.f) * mv0, fmaxf(rA.y, 0.f) * mv1,
                               fmaxf(rB.x, 0.f) * mv2, fmaxf(rB.y, 0.f) * mv3);
      }
    }
    __syncthreads();
    #pragma unroll
    for (int q = 0; q < 2; q++)
      #pragma unroll
      for (int c = 0; c < 4; c++)
        *(float4*)&sb->fT[q][h0 + c][p0] = sv[q][c];
  }
  __syncthreads();

  // ===== feat = max-pool over points =======================================
  {
    int q = tid >> 6, ch = tid & 63;
    const float4* row = (const float4*)&sb->fT[q][ch][0];
    float m = 0.f;
    #pragma unroll
    for (int g = 0; g < 8; g++) {
      float4 v = row[g];
      m = fmaxf(m, fmaxf(fmaxf(v.x, v.y), fmaxf(v.z, v.w)));
    }
    (&sb->feat2[ch].x)[q] = m;
  }
  __syncthreads();

  // ===== head layer 1: hid = relu(feat @ o1_w + o1_b), split-k =============
  {
    int half = tid >> 6, ch = tid & 63;
    int kb = half * 32;
    ull a = 0ull;
    #pragma unroll 8
    for (int k = 0; k < 32; k++) {
      float wv = __ldg(&o1_w[(kb + k) * H + ch]);
      a = fma2(*(const ull*)&sb->feat2[kb + k], dup2(wv), a);
    }
    sb->part[half][ch] = a;
  }
  __syncthreads();
  if (tid < 64) {
    ull s = fma2(sb->part[0][tid], ONE, sb->part[1][tid]);
    s = fma2(dup2(__ldg(&o1_b[tid])), ONE, s);
    float2 r = unpk(s);
    sb->hid2[tid] = make_float2(fmaxf(r.x, 0.f), fmaxf(r.y, 0.f));
  }
  __syncthreads();

  // ===== head layer 2: out = hid @ o2_w + o2_b, j = tid ====================
  {
    float vf0 = sb->s_valid[0] ? 1.f : 0.f;
    float vf1 = sb->s_valid[1] ? 1.f : 0.f;
    ull a = dup2(__ldg(&o2_b[tid]));
    #pragma unroll 8
    for (int k = 0; k < H; k++) {
      float wv = __ldg(&o2_w[k * OUTC + tid]);
      a = fma2(*(const ull*)&sb->hid2[k], dup2(wv), a);
    }
    float2 r = unpk(a);
    out[(long long)(2 * blk) * OUTC + tid]     = r.x * vf0;
    out[(long long)(2 * blk + 1) * OUTC + tid] = r.y * vf1;
  }
}

extern "C" void kernel_launch(void* const* d_in, const int* in_sizes, int n_in,
                              void* d_out, int out_size)
{
  (void)in_sizes; (void)n_in;
  const int n_poly = out_size / OUTC;   // B*N = 16384 (even)
  // Stage main-loop weights into the constant bank (D2D memcpy nodes;
  // graph-capturable, allocation-free, deterministic).
  cudaMemcpyToSymbolAsync(cw_pre, d_in[2],  Cin * H * sizeof(float),   0,
                          cudaMemcpyDeviceToDevice);
  cudaMemcpyToSymbolAsync(cw_m1,  d_in[8],  2 * H * H * sizeof(float), 0,
                          cudaMemcpyDeviceToDevice);
  cudaMemcpyToSymbolAsync(cw_m2,  d_in[14], H * H * sizeof(float),     0,
                          cudaMemcpyDeviceToDevice);
  pnet_kernel<<<n_poly / 2, 128>>>(
      (const float*)d_in[0],  d_in[1],
      (const float*)d_in[3],
      (const float*)d_in[4],  (const float*)d_in[5],
      (const float*)d_in[6],  (const float*)d_in[7],
      (const float*)d_in[9],
      (const float*)d_in[10], (const float*)d_in[11],
      (const float*)d_in[12], (const float*)d_in[13],
      (const float*)d_in[15],
      (const float*)d_in[16], (const float*)d_in[17],
      (const float*)d_in[18], (const float*)d_in[19],
      (const float*)d_in[20], (const float*)d_in[21],
      (const float*)d_in[22], (const float*)d_in[23],
      (float*)d_out);
}